// round 1
// baseline (speedup 1.0000x reference)
#include <cuda_runtime.h>
#include <cuda_bf16.h>
#include <math.h>

// Shapes (fixed by the problem): B*S = 8192 tokens, H = 4096, I = 14336.
#define HDIM 4096
#define IDIM 14336
#define TH   0.5f

// 8192 * 14336 fp32 scratch for the masked activation (448 MiB).
// __device__ global = allocation-guard-legal scratch.
__device__ static float g_act[117440512ull];

// ---------------------------------------------------------------------------
// Pass 1: up = x @ w_up^T, gate = x @ w_gate^T (shared x tile),
//         act = mask ? silu(gate) * up : 0, mask = |up*avg_gate| >= 0.5
// Tile: BM=128, BN=64, BK=16; 256 threads; per-thread 8x4 microtile x2 outputs.
// ---------------------------------------------------------------------------
#define BM1 128
#define BN1 64
#define BK1 16

__global__ __launch_bounds__(256, 2)
void mlp_pass1(const float* __restrict__ x,
               const float* __restrict__ wg,
               const float* __restrict__ wu,
               const float* __restrict__ ag)
{
    __shared__ float As[BK1][BM1];
    __shared__ float Bu[BK1][BN1];
    __shared__ float Bg[BK1][BN1];

    const int m0 = blockIdx.y * BM1;
    const int n0 = blockIdx.x * BN1;
    const int tid = threadIdx.x;
    const int tx = tid & 15;    // N direction (4 cols each)
    const int ty = tid >> 4;    // M direction (8 rows each)

    float up[8][4];
    float gt[8][4];
#pragma unroll
    for (int i = 0; i < 8; ++i)
#pragma unroll
        for (int j = 0; j < 4; ++j) { up[i][j] = 0.f; gt[i][j] = 0.f; }

    // A-tile load mapping: 128x16 = 512 float4, 2 per thread
    const int ar0 = (tid + 0)   >> 2, ac0 = (tid + 0)   & 3;
    const int ar1 = (tid + 256) >> 2, ac1 = (tid + 256) & 3;
    // B-tile load mapping: 64x16 = 256 float4, 1 per thread
    const int br = tid >> 2, bc = tid & 3;

    for (int k0 = 0; k0 < HDIM; k0 += BK1) {
        // load x tile (transposed into As[k][m])
        float4 va0 = *(const float4*)(x + (size_t)(m0 + ar0) * HDIM + k0 + ac0 * 4);
        float4 va1 = *(const float4*)(x + (size_t)(m0 + ar1) * HDIM + k0 + ac1 * 4);
        // load w_up / w_gate tiles (transposed)
        float4 vu = *(const float4*)(wu + (size_t)(n0 + br) * HDIM + k0 + bc * 4);
        float4 vg = *(const float4*)(wg + (size_t)(n0 + br) * HDIM + k0 + bc * 4);

        As[ac0 * 4 + 0][ar0] = va0.x; As[ac0 * 4 + 1][ar0] = va0.y;
        As[ac0 * 4 + 2][ar0] = va0.z; As[ac0 * 4 + 3][ar0] = va0.w;
        As[ac1 * 4 + 0][ar1] = va1.x; As[ac1 * 4 + 1][ar1] = va1.y;
        As[ac1 * 4 + 2][ar1] = va1.z; As[ac1 * 4 + 3][ar1] = va1.w;
        Bu[bc * 4 + 0][br] = vu.x; Bu[bc * 4 + 1][br] = vu.y;
        Bu[bc * 4 + 2][br] = vu.z; Bu[bc * 4 + 3][br] = vu.w;
        Bg[bc * 4 + 0][br] = vg.x; Bg[bc * 4 + 1][br] = vg.y;
        Bg[bc * 4 + 2][br] = vg.z; Bg[bc * 4 + 3][br] = vg.w;
        __syncthreads();

#pragma unroll
        for (int k = 0; k < BK1; ++k) {
            float a[8], bu4[4], bg4[4];
#pragma unroll
            for (int i = 0; i < 8; ++i) a[i] = As[k][ty * 8 + i];
#pragma unroll
            for (int j = 0; j < 4; ++j) { bu4[j] = Bu[k][tx * 4 + j]; bg4[j] = Bg[k][tx * 4 + j]; }
#pragma unroll
            for (int i = 0; i < 8; ++i)
#pragma unroll
                for (int j = 0; j < 4; ++j) {
                    up[i][j] = fmaf(a[i], bu4[j], up[i][j]);
                    gt[i][j] = fmaf(a[i], bg4[j], gt[i][j]);
                }
        }
        __syncthreads();
    }

    // epilogue: mask + silu, vectorized store of 4 consecutive n
    float a4[4];
#pragma unroll
    for (int j = 0; j < 4; ++j) a4[j] = ag[n0 + tx * 4 + j];

#pragma unroll
    for (int i = 0; i < 8; ++i) {
        float4 v;
        float r[4];
#pragma unroll
        for (int j = 0; j < 4; ++j) {
            float u = up[i][j];
            float g = gt[i][j];
            float o = 0.f;
            if (fabsf(u * a4[j]) >= TH) {
                float s = g / (1.f + expf(-g));   // silu(gate)
                o = s * u;
            }
            r[j] = o;
        }
        v.x = r[0]; v.y = r[1]; v.z = r[2]; v.w = r[3];
        *(float4*)(&g_act[(size_t)(m0 + ty * 8 + i) * IDIM + n0 + tx * 4]) = v;
    }
}

// ---------------------------------------------------------------------------
// Pass 2: out[t,h] = sum_i act[t,i] * w_down[h,i]
// Tile: BM=128, BN=128, BK=16; 256 threads; 8x8 microtile.
// ---------------------------------------------------------------------------
#define BM2 128
#define BN2 128
#define BK2 16

__global__ __launch_bounds__(256, 2)
void mlp_pass2(const float* __restrict__ wd,
               float* __restrict__ out)
{
    __shared__ float As[BK2][BM2];
    __shared__ float Bs[BK2][BN2];

    const int m0 = blockIdx.y * BM2;
    const int n0 = blockIdx.x * BN2;
    const int tid = threadIdx.x;
    const int tx = tid & 15;    // N direction (8 cols)
    const int ty = tid >> 4;    // M direction (8 rows)

    float acc[8][8];
#pragma unroll
    for (int i = 0; i < 8; ++i)
#pragma unroll
        for (int j = 0; j < 8; ++j) acc[i][j] = 0.f;

    const int r0 = (tid + 0)   >> 2, c0 = (tid + 0)   & 3;
    const int r1 = (tid + 256) >> 2, c1 = (tid + 256) & 3;

    for (int k0 = 0; k0 < IDIM; k0 += BK2) {
        float4 va0 = *(const float4*)(&g_act[(size_t)(m0 + r0) * IDIM + k0 + c0 * 4]);
        float4 va1 = *(const float4*)(&g_act[(size_t)(m0 + r1) * IDIM + k0 + c1 * 4]);
        float4 vb0 = *(const float4*)(wd + (size_t)(n0 + r0) * IDIM + k0 + c0 * 4);
        float4 vb1 = *(const float4*)(wd + (size_t)(n0 + r1) * IDIM + k0 + c1 * 4);

        As[c0 * 4 + 0][r0] = va0.x; As[c0 * 4 + 1][r0] = va0.y;
        As[c0 * 4 + 2][r0] = va0.z; As[c0 * 4 + 3][r0] = va0.w;
        As[c1 * 4 + 0][r1] = va1.x; As[c1 * 4 + 1][r1] = va1.y;
        As[c1 * 4 + 2][r1] = va1.z; As[c1 * 4 + 3][r1] = va1.w;
        Bs[c0 * 4 + 0][r0] = vb0.x; Bs[c0 * 4 + 1][r0] = vb0.y;
        Bs[c0 * 4 + 2][r0] = vb0.z; Bs[c0 * 4 + 3][r0] = vb0.w;
        Bs[c1 * 4 + 0][r1] = vb1.x; Bs[c1 * 4 + 1][r1] = vb1.y;
        Bs[c1 * 4 + 2][r1] = vb1.z; Bs[c1 * 4 + 3][r1] = vb1.w;
        __syncthreads();

#pragma unroll
        for (int k = 0; k < BK2; ++k) {
            float a[8], b[8];
#pragma unroll
            for (int i = 0; i < 8; ++i) a[i] = As[k][ty * 8 + i];
#pragma unroll
            for (int j = 0; j < 8; ++j) b[j] = Bs[k][tx * 8 + j];
#pragma unroll
            for (int i = 0; i < 8; ++i)
#pragma unroll
                for (int j = 0; j < 8; ++j) acc[i][j] = fmaf(a[i], b[j], acc[i][j]);
        }
        __syncthreads();
    }

#pragma unroll
    for (int i = 0; i < 8; ++i) {
        float4 v0, v1;
        v0.x = acc[i][0]; v0.y = acc[i][1]; v0.z = acc[i][2]; v0.w = acc[i][3];
        v1.x = acc[i][4]; v1.y = acc[i][5]; v1.z = acc[i][6]; v1.w = acc[i][7];
        float* p = out + (size_t)(m0 + ty * 8 + i) * HDIM + n0 + tx * 8;
        *(float4*)(p + 0) = v0;
        *(float4*)(p + 4) = v1;
    }
}

// ---------------------------------------------------------------------------
// Launch
// inputs (metadata order): x, w_gate, w_up, w_down, avg_gate
// ---------------------------------------------------------------------------
extern "C" void kernel_launch(void* const* d_in, const int* in_sizes, int n_in,
                              void* d_out, int out_size)
{
    const float* x  = (const float*)d_in[0];
    const float* wg = (const float*)d_in[1];
    const float* wu = (const float*)d_in[2];
    const float* wd = (const float*)d_in[3];
    const float* ag = (const float*)d_in[4];
    float* out = (float*)d_out;

    const int T = in_sizes[0] / HDIM;   // 8192 tokens

    dim3 grid1(IDIM / BN1, T / BM1);    // (224, 64)
    mlp_pass1<<<grid1, 256>>>(x, wg, wu, ag);

    dim3 grid2(HDIM / BN2, T / BM2);    // (32, 64)
    mlp_pass2<<<grid2, 256>>>(wd, out);
}

// round 5
// speedup vs baseline: 2.9945x; 2.9945x over previous
#include <cuda_runtime.h>
#include <cstdint>
#include <math.h>

// ---------------------------------------------------------------------------
// Shapes (fixed): tokens T=8192, H=4096, I=14336
// ---------------------------------------------------------------------------
#define HDIM 4096
#define IDIM 14336
#define TH   0.5f
#define BAND 0.008f                 // borderline-mask band on |u*a| around TH

#define TW 36                       // padded smem row stride (32 data + 4 pad)
#define TILE_FLOATS (128 * TW)
#define TILE_BYTES  (TILE_FLOATS * 4)

// 448 MiB activation scratch (fp32)
__device__ float g_act[117440512ull];

// ---------------------------------------------------------------------------
// helpers
// ---------------------------------------------------------------------------
__device__ __forceinline__ uint32_t smem_u32(const void* p) {
    uint32_t a;
    asm("{ .reg .u64 t; cvta.to.shared.u64 t, %1; cvt.u32.u64 %0, t; }" : "=r"(a) : "l"(p));
    return a;
}
__device__ __forceinline__ uint32_t f2tf(float x) {  // RNA round to tf32
    uint32_t o;
    asm("cvt.rna.tf32.f32 %0, %1;" : "=r"(o) : "f"(x));
    return o;
}
__device__ __forceinline__ void cp_async16(uint32_t dst, const void* src) {
    asm volatile("cp.async.cg.shared.global [%0], [%1], 16;" :: "r"(dst), "l"(src) : "memory");
}
__device__ __forceinline__ void cp_commit() {
    asm volatile("cp.async.commit_group;" ::: "memory");
}
template <int N> __device__ __forceinline__ void cp_wait() {
    asm volatile("cp.async.wait_group %0;" :: "n"(N) : "memory");
}

// m16n8k8 tf32 mma
__device__ __forceinline__ void mma8(float* c, const uint32_t* a, const uint32_t* b) {
    asm volatile(
        "mma.sync.aligned.m16n8k8.row.col.f32.tf32.tf32.f32 "
        "{%0,%1,%2,%3}, {%4,%5,%6,%7}, {%8,%9}, {%0,%1,%2,%3};"
        : "+f"(c[0]), "+f"(c[1]), "+f"(c[2]), "+f"(c[3])
        : "r"(a[0]), "r"(a[1]), "r"(a[2]), "r"(a[3]), "r"(b[0]), "r"(b[1]));
}

__device__ __forceinline__ float masked_silu(float u, float g, float a) {
    float o = 0.f;
    if (fabsf(u * a) >= TH) o = u * (g / (1.f + expf(-g)));
    return o;
}

// exact fp32 dot(x_row, wu_row) over HDIM, warp-cooperative; all lanes get sum
__device__ __noinline__ float warp_dot(const float* __restrict__ xr,
                                       const float* __restrict__ wr, int lane) {
    const float4* x4 = (const float4*)xr;
    const float4* w4 = (const float4*)wr;
    float s = 0.f;
#pragma unroll 4
    for (int i = lane; i < HDIM / 4; i += 32) {
        float4 a = x4[i], b = w4[i];
        s = fmaf(a.x, b.x, s); s = fmaf(a.y, b.y, s);
        s = fmaf(a.z, b.z, s); s = fmaf(a.w, b.w, s);
    }
#pragma unroll
    for (int off = 16; off; off >>= 1) s += __shfl_xor_sync(0xffffffffu, s, off);
    return s;
}

// ---------------------------------------------------------------------------
// P1: up = x@wu^T (1xtf32), gate = x@wg^T (1xtf32) -> masked act (fp32)
// Borderline mask decisions (|u*a| within BAND of TH) recomputed exactly in fp32.
// CTA 128x128, 8 warps, warp tile 64x32
// ---------------------------------------------------------------------------
#define P1_STAGES 3
#define P1_STAGE_FLOATS (3 * TILE_FLOATS)
#define P1_SMEM (P1_STAGES * P1_STAGE_FLOATS * 4)   // 165888 B

__global__ __launch_bounds__(256, 1)
void p1_kernel(const float* __restrict__ x, const float* __restrict__ wg,
               const float* __restrict__ wu, const float* __restrict__ ag,
               float* __restrict__ act)
{
    extern __shared__ float sm[];

    const int per = 16 * 112;
    const int grp = blockIdx.x / per;
    const int w   = blockIdx.x % per;
    const int m0  = (grp * 16 + (w % 16)) * 128;
    const int n0  = (w / 16) * 128;

    const int tid  = threadIdx.x;
    const int wid  = tid >> 5;
    const int lane = tid & 31;
    const int wm   = wid >> 2;
    const int wn   = wid & 3;
    const int ar   = lane >> 2;
    const int ac   = lane & 3;

    float upc[4][4][4];
    float gtc[4][4][4];
#pragma unroll
    for (int t = 0; t < 4; ++t)
#pragma unroll
        for (int u = 0; u < 4; ++u)
#pragma unroll
            for (int q = 0; q < 4; ++q) { upc[t][u][q] = 0.f; gtc[t][u][q] = 0.f; }

    const int NCH = HDIM / 32;

    auto load_chunk = [&](int ch) {
        const int st = ch % P1_STAGES;
        const uint32_t sb = smem_u32(sm + st * P1_STAGE_FLOATS);
        const float* xs  = x  + (size_t)m0 * HDIM + ch * 32;
        const float* wus = wu + (size_t)n0 * HDIM + ch * 32;
        const float* wgs = wg + (size_t)n0 * HDIM + ch * 32;
#pragma unroll
        for (int q = 0; q < 4; ++q) {
            int lin = q * 256 + tid;
            int r = lin >> 3, c = lin & 7;
            uint32_t doff = (uint32_t)(r * TW + c * 4) * 4;
            cp_async16(sb + doff,                  xs  + (size_t)r * HDIM + c * 4);
            cp_async16(sb + TILE_BYTES + doff,     wus + (size_t)r * HDIM + c * 4);
            cp_async16(sb + 2 * TILE_BYTES + doff, wgs + (size_t)r * HDIM + c * 4);
        }
        cp_commit();
    };

    load_chunk(0);
    load_chunk(1);

    for (int ch = 0; ch < NCH; ++ch) {
        cp_wait<P1_STAGES - 2>();
        __syncthreads();
        if (ch + P1_STAGES - 1 < NCH) load_chunk(ch + P1_STAGES - 1);
        else cp_commit();

        const float* base = sm + (ch % P1_STAGES) * P1_STAGE_FLOATS;
        const float* sX  = base;
        const float* sWu = base + TILE_FLOATS;
        const float* sWg = base + 2 * TILE_FLOATS;

#pragma unroll
        for (int s8 = 0; s8 < 4; ++s8) {
            const int k0 = s8 * 8;
            uint32_t xf[4][4];
#pragma unroll
            for (int t = 0; t < 4; ++t) {
                const int mb = wm * 64 + t * 16;
                xf[t][0] = f2tf(sX[(mb + ar)     * TW + k0 + ac]);
                xf[t][1] = f2tf(sX[(mb + ar + 8) * TW + k0 + ac]);
                xf[t][2] = f2tf(sX[(mb + ar)     * TW + k0 + ac + 4]);
                xf[t][3] = f2tf(sX[(mb + ar + 8) * TW + k0 + ac + 4]);
            }
            uint32_t uf[4][2], gf[4][2];
#pragma unroll
            for (int u = 0; u < 4; ++u) {
                const int nb = wn * 32 + u * 8;
                uf[u][0] = f2tf(sWu[(nb + ar) * TW + k0 + ac]);
                uf[u][1] = f2tf(sWu[(nb + ar) * TW + k0 + ac + 4]);
                gf[u][0] = f2tf(sWg[(nb + ar) * TW + k0 + ac]);
                gf[u][1] = f2tf(sWg[(nb + ar) * TW + k0 + ac + 4]);
            }
#pragma unroll
            for (int t = 0; t < 4; ++t)
#pragma unroll
                for (int u = 0; u < 4; ++u) {
                    mma8(upc[t][u], xf[t], uf[u]);
                    mma8(gtc[t][u], xf[t], gf[u]);
                }
        }
    }

    // ---------------- epilogue: borderline recompute + mask + silu ----------
#pragma unroll
    for (int t = 0; t < 4; ++t) {
#pragma unroll
        for (int u = 0; u < 4; ++u) {
            const int gr = m0 + wm * 64 + t * 16 + ar;
            const int gc = n0 + wn * 32 + u * 8 + 2 * ac;
            const float a0 = __ldg(ag + gc);
            const float a1 = __ldg(ag + gc + 1);
            float uv[4] = {upc[t][u][0], upc[t][u][1], upc[t][u][2], upc[t][u][3]};
            float gv[4] = {gtc[t][u][0], gtc[t][u][1], gtc[t][u][2], gtc[t][u][3]};
            float av[4] = {a0, a1, a0, a1};
            int   rw[4] = {gr, gr, gr + 8, gr + 8};
            int   cl[4] = {gc, gc + 1, gc, gc + 1};
#pragma unroll
            for (int q = 0; q < 4; ++q) {
                bool flag = fabsf(fabsf(uv[q] * av[q]) - TH) < BAND;
                unsigned bal = __ballot_sync(0xffffffffu, flag);
                while (bal) {
                    int src = __ffs(bal) - 1; bal &= bal - 1;
                    int rr = __shfl_sync(0xffffffffu, rw[q], src);
                    int cc = __shfl_sync(0xffffffffu, cl[q], src);
                    float s = warp_dot(x + (size_t)rr * HDIM, wu + (size_t)cc * HDIM, lane);
                    if (lane == src) uv[q] = s;   // exact fp32 up for mask & value
                }
            }
            float2 v0, v1;
            v0.x = masked_silu(uv[0], gv[0], av[0]);
            v0.y = masked_silu(uv[1], gv[1], av[1]);
            v1.x = masked_silu(uv[2], gv[2], av[2]);
            v1.y = masked_silu(uv[3], gv[3], av[3]);
            *(float2*)&act[(size_t)rw[0] * IDIM + gc] = v0;
            *(float2*)&act[(size_t)rw[2] * IDIM + gc] = v1;
        }
    }
}

// ---------------------------------------------------------------------------
// P2: out = act @ wd^T, 1xtf32
// CTA 128x256, 8 warps, warp tile 64x64
// ---------------------------------------------------------------------------
#define P2_STAGES 4
#define P2_B_FLOATS (256 * TW)
#define P2_STAGE_FLOATS (TILE_FLOATS + P2_B_FLOATS)
#define P2_SMEM (P2_STAGES * P2_STAGE_FLOATS * 4)   // 221184 B

__global__ __launch_bounds__(256, 1)
void p2_kernel(const float* __restrict__ act, const float* __restrict__ wd,
               float* __restrict__ out)
{
    extern __shared__ float sm[];

    const int per = 16 * 16;
    const int grp = blockIdx.x / per;
    const int w   = blockIdx.x % per;
    const int m0  = (grp * 16 + (w % 16)) * 128;
    const int n0  = (w / 16) * 256;

    const int tid  = threadIdx.x;
    const int wid  = tid >> 5;
    const int lane = tid & 31;
    const int wm   = wid >> 2;
    const int wn   = wid & 3;
    const int ar   = lane >> 2;
    const int ac   = lane & 3;

    float acc[4][8][4];
#pragma unroll
    for (int t = 0; t < 4; ++t)
#pragma unroll
        for (int u = 0; u < 8; ++u)
#pragma unroll
            for (int q = 0; q < 4; ++q) acc[t][u][q] = 0.f;

    const int NCH = IDIM / 32;

    auto load_chunk = [&](int ch) {
        const int st = ch % P2_STAGES;
        const uint32_t sb = smem_u32(sm + st * P2_STAGE_FLOATS);
        const float* as = act + (size_t)m0 * IDIM + ch * 32;
        const float* bs = wd  + (size_t)n0 * IDIM + ch * 32;
#pragma unroll
        for (int q = 0; q < 4; ++q) {
            int lin = q * 256 + tid;
            int r = lin >> 3, c = lin & 7;
            cp_async16(sb + (uint32_t)(r * TW + c * 4) * 4, as + (size_t)r * IDIM + c * 4);
        }
#pragma unroll
        for (int q = 0; q < 8; ++q) {
            int lin = q * 256 + tid;
            int r = lin >> 3, c = lin & 7;
            cp_async16(sb + TILE_BYTES + (uint32_t)(r * TW + c * 4) * 4,
                       bs + (size_t)r * IDIM + c * 4);
        }
        cp_commit();
    };

    load_chunk(0);
    load_chunk(1);
    load_chunk(2);

    for (int ch = 0; ch < NCH; ++ch) {
        cp_wait<P2_STAGES - 2>();
        __syncthreads();
        if (ch + P2_STAGES - 1 < NCH) load_chunk(ch + P2_STAGES - 1);
        else cp_commit();

        const float* base = sm + (ch % P2_STAGES) * P2_STAGE_FLOATS;
        const float* sA = base;
        const float* sB = base + TILE_FLOATS;

#pragma unroll
        for (int s8 = 0; s8 < 4; ++s8) {
            const int k0 = s8 * 8;
            uint32_t af[4][4];
#pragma unroll
            for (int t = 0; t < 4; ++t) {
                const int mb = wm * 64 + t * 16;
                af[t][0] = f2tf(sA[(mb + ar)     * TW + k0 + ac]);
                af[t][1] = f2tf(sA[(mb + ar + 8) * TW + k0 + ac]);
                af[t][2] = f2tf(sA[(mb + ar)     * TW + k0 + ac + 4]);
                af[t][3] = f2tf(sA[(mb + ar + 8) * TW + k0 + ac + 4]);
            }
            uint32_t bf[8][2];
#pragma unroll
            for (int u = 0; u < 8; ++u) {
                const int nb = wn * 64 + u * 8;
                bf[u][0] = f2tf(sB[(nb + ar) * TW + k0 + ac]);
                bf[u][1] = f2tf(sB[(nb + ar) * TW + k0 + ac + 4]);
            }
#pragma unroll
            for (int t = 0; t < 4; ++t)
#pragma unroll
                for (int u = 0; u < 8; ++u)
                    mma8(acc[t][u], af[t], bf[u]);
        }
    }

#pragma unroll
    for (int t = 0; t < 4; ++t) {
#pragma unroll
        for (int u = 0; u < 8; ++u) {
            const int gr = m0 + wm * 64 + t * 16 + ar;
            const int gc = n0 + wn * 64 + u * 8 + 2 * ac;
            float2 v0, v1;
            v0.x = acc[t][u][0]; v0.y = acc[t][u][1];
            v1.x = acc[t][u][2]; v1.y = acc[t][u][3];
            *(float2*)&out[(size_t)gr * HDIM + gc]       = v0;
            *(float2*)&out[(size_t)(gr + 8) * HDIM + gc] = v1;
        }
    }
}

// ---------------------------------------------------------------------------
// launch: inputs x, w_gate, w_up, w_down, avg_gate
// ---------------------------------------------------------------------------
extern "C" void kernel_launch(void* const* d_in, const int* in_sizes, int n_in,
                              void* d_out, int out_size)
{
    const float* x  = (const float*)d_in[0];
    const float* wg = (const float*)d_in[1];
    const float* wu = (const float*)d_in[2];
    const float* wd = (const float*)d_in[3];
    const float* ag = (const float*)d_in[4];
    float* out = (float*)d_out;

    float* act;
    cudaGetSymbolAddress((void**)&act, g_act);

    cudaFuncSetAttribute(p1_kernel, cudaFuncAttributeMaxDynamicSharedMemorySize, P1_SMEM);
    cudaFuncSetAttribute(p2_kernel, cudaFuncAttributeMaxDynamicSharedMemorySize, P2_SMEM);

    p1_kernel<<<7168, 256, P1_SMEM>>>(x, wg, wu, ag, act);
    p2_kernel<<<1024, 256, P2_SMEM>>>(act, wd, out);
}